// round 17
// baseline (speedup 1.0000x reference)
#include <cuda_runtime.h>
#include <cuda_fp16.h>
#include <math.h>

#define NV 16

// ---------------- device scratch ----------------
__device__ float g_pm[240];
__device__ float g_hp[16];
__device__ float g_part[240 * 4];
__device__ unsigned g_wpack[16 * 5120];    // per-v fp16 fragments: W1 1024 + W2 4096
__device__ float g_gram[32 * 256];
__device__ float g_colsum[32 * 16];

// packed f32x2 FMA (pairs path)
union F2U { float2 f; unsigned long long u; };
__device__ __forceinline__ float2 ffma2(float2 a, float2 b, float2 c) {
    F2U au, bu, cu, du;
    au.f = a; bu.f = b; cu.f = c;
    asm("fma.rn.f32x2 %0, %1, %2, %3;" : "=l"(du.u) : "l"(au.u), "l"(bu.u), "l"(cu.u));
    return du.f;
}

// fp16 m16n8k16 MMA, fp32 accumulate
__device__ __forceinline__ void mma_f16(float* d, const unsigned* a, const unsigned* b) {
    asm volatile(
        "mma.sync.aligned.m16n8k16.row.col.f32.f16.f16.f32 "
        "{%0,%1,%2,%3}, {%4,%5,%6,%7}, {%8,%9}, {%0,%1,%2,%3};"
        : "+f"(d[0]), "+f"(d[1]), "+f"(d[2]), "+f"(d[3])
        : "r"(a[0]), "r"(a[1]), "r"(a[2]), "r"(a[3]), "r"(b[0]), "r"(b[1]));
}

__device__ __forceinline__ unsigned pack2h(float a, float b) {
    __half2 h = __floats2half2_rn(a, b);
    return *reinterpret_cast<unsigned*>(&h);
}
__device__ __forceinline__ float hround(float x) {
    return __half2float(__float2half_rn(x));
}

// ---------------- Kernel P: wpack (0-63) + avg/Gram (64-95) + PAIRS (96-215) ----------------
__global__ void __launch_bounds__(256) k_prep(
    const float* __restrict__ Wm1, const float* __restrict__ Wm2,
    const float* __restrict__ data,
    const float* __restrict__ Wt1, const float* __restrict__ bt1,
    const float* __restrict__ Wt2, const float* __restrict__ bt2)
{
    extern __shared__ float sm[];
    int bid = blockIdx.x, tid = threadIdx.x;
    if (bid < 64) {
        int v = bid >> 2, quarter = bid & 3;
        unsigned* dst = g_wpack + v * 5120;
        {
            int idx = quarter * 256 + tid;
            int nt = idx >> 6, lane = (idx >> 1) & 31, r = idx & 1;
            int lg = lane >> 2, lq = lane & 3;
            int n = nt * 8 + lg, kp = lq + 4 * r;
            int k0 = 2 * kp, k1 = 2 * kp + 1;
            float w0 = (k0 < 15) ? Wm1[v * 1920 + k0 * 128 + n] : 0.f;
            float w1 = (k1 < 15) ? Wm1[v * 1920 + k1 * 128 + n] : 0.f;
            dst[idx] = pack2h(w0, w1);
        }
        for (int idx = quarter * 1024 + tid; idx < quarter * 1024 + 1024; idx += 256) {
            int ks = idx >> 9, nt = (idx >> 6) & 7, lane = (idx >> 1) & 31, r = idx & 1;
            int lg = lane >> 2, lq = lane & 3;
            int n = nt * 8 + lg, kp = ks * 8 + lq + 4 * r;
            int k0 = 2 * kp, k1 = 2 * kp + 1;
            float w0 = Wm2[v * 8192 + k0 * 64 + n];
            float w1 = Wm2[v * 8192 + k1 * 64 + n];
            dst[1024 + idx] = pack2h(w0, w1);
        }
    } else if (bid < 96) {
        __shared__ float avs[256];
        int q = bid - 64;
        float s = 0.f;
#pragma unroll
        for (int b = 0; b < 16; b++) s += data[b * 8192 + q * 256 + tid];
        avs[tid] = s * (1.f / 16.f);
        __syncthreads();
        int i = tid >> 4, j = tid & 15;
        float g = 0.f;
#pragma unroll
        for (int r = 0; r < 16; r++) g += avs[r * 16 + i] * avs[r * 16 + j];
        g_gram[q * 256 + tid] = g;
        if (tid < 16) {
            float cs = 0.f;
#pragma unroll
            for (int r = 0; r < 16; r++) cs += avs[r * 16 + tid];
            g_colsum[q * 16 + tid] = cs;
        }
    } else {
        // ================= PAIRS (warp-per-pair, lane-per-sample) =================
        float* rows = sm;                       // [128][17] = 2176 floats
        float* wpk  = sm + 2176;                // [8 pairs][16 ch2][8] = 1024 floats
        int pb = bid - 96;                      // 0..119
        int squad = pb / 30;                    // 0..3 -> samples squad*2048
        int pairbase = (pb - squad * 30) * 8;
        int w = tid >> 5, lane = tid & 31;

        // stage weights: [pl][ch2][wa0,wa1,wb0,wb1,b0,b1,w20,w21]
        {
            int t4 = tid * 4;
#pragma unroll
            for (int u = 0; u < 4; u++) {
                int idx = t4 + u;
                int pl = idx >> 7, rem = idx & 127;
                int ch2 = rem >> 3, f = rem & 7;
                int p = pairbase + pl;
                float val;
                if (f < 2)      val = Wt1[p * 64 + 2 * ch2 + f];
                else if (f < 4) val = Wt1[p * 64 + 32 + 2 * ch2 + (f - 2)];
                else if (f < 6) val = bt1[p * 32 + 2 * ch2 + (f - 4)];
                else            val = Wt2[p * 32 + 2 * ch2 + (f - 6)];
                wpk[idx] = val;
            }
        }

        int p = pairbase + w;
        int pi = p / 15, rr = p - pi * 15;
        int pj = rr + (rr >= pi ? 1 : 0);
        float b2v = bt2[p];
        const float* wrow = wpk + w * 128;
        float accs = 0.f;

        for (int c = 0; c < 16; c++) {
            __syncthreads();
            int sbase = squad * 2048 + c * 128;
            {
                int t = tid;
#pragma unroll
                for (int u = 0; u < 2; u++) {
                    int s = t >> 2, q = t & 3;
                    float4 v = *(const float4*)(data + (sbase + s) * 16 + q * 4);
                    float* dst = rows + s * 17 + q * 4;
                    dst[0] = v.x; dst[1] = v.y; dst[2] = v.z; dst[3] = v.w;
                    t += 256;
                }
            }
            __syncthreads();

#pragma unroll
            for (int it = 0; it < 4; it++) {
                int s = it * 32 + lane;
                float xi = rows[s * 17 + pi], xj = rows[s * 17 + pj];
                float2 xi2 = make_float2(xi, xi), xj2 = make_float2(xj, xj);
                float2 sv0 = make_float2(0.f, 0.f), sv1 = make_float2(0.f, 0.f);
                float2 sv2 = make_float2(0.f, 0.f), sv3 = make_float2(0.f, 0.f);
#pragma unroll
                for (int ch2 = 0; ch2 < 16; ch2 += 4) {
#pragma unroll
                    for (int g = 0; g < 4; g++) {
                        float4 wv = *(const float4*)(wrow + (ch2 + g) * 8);       // broadcast
                        float4 bv = *(const float4*)(wrow + (ch2 + g) * 8 + 4);   // broadcast
                        float2 h = ffma2(xi2, make_float2(wv.x, wv.y), make_float2(bv.x, bv.y));
                        h = ffma2(xj2, make_float2(wv.z, wv.w), h);
                        h.x = fmaxf(h.x, 0.f); h.y = fmaxf(h.y, 0.f);
                        float2 w2 = make_float2(bv.z, bv.w);
                        if (g == 0) sv0 = ffma2(h, w2, sv0);
                        else if (g == 1) sv1 = ffma2(h, w2, sv1);
                        else if (g == 2) sv2 = ffma2(h, w2, sv2);
                        else sv3 = ffma2(h, w2, sv3);
                    }
                }
                float sv = ((sv0.x + sv0.y) + (sv1.x + sv1.y))
                         + ((sv2.x + sv2.y) + (sv3.x + sv3.y));
                accs += __fdividef(1.f, 1.f + __expf(-(sv + b2v)));
            }
        }
#pragma unroll
        for (int off = 16; off > 0; off >>= 1)
            accs += __shfl_xor_sync(0xffffffffu, accs, off);
        if (lane == 0) g_part[p * 4 + squad] = accs;
    }
}

// ---------------- Kernel A: score finalize + corr -> MLP -> adj -> masks ----------------
__global__ void __launch_bounds__(1024) k_adj(
    const float* __restrict__ Ws1, const float* __restrict__ bs1,
    const float* __restrict__ Ws2, const float* __restrict__ bs2,
    const float* __restrict__ Ws3, const float* __restrict__ bs3,
    float* __restrict__ out_adj, float* __restrict__ out_scores)
{
    __shared__ float scratch[1024];
    __shared__ float cm[16];
    __shared__ float covs[256];
    __shared__ float corr_s[256];
    __shared__ float h1s[256];
    __shared__ float h2s[128];
    __shared__ float adj_s[256];
    __shared__ float pms[240];

    int tid = threadIdx.x;
    // ---- score finalize (pairs partials from k_prep) ----
    if (tid < 240) {
        float4 v = *(const float4*)(g_part + tid * 4);
        float s = (v.x + v.y) + (v.z + v.w);
        int pi = tid / 15, r = tid - pi * 15;
        int pj = r + (r >= pi ? 1 : 0);
        out_scores[pi * 16 + pj] = s * (1.f / 8192.f);
    }
    if (tid < 16) out_scores[tid * 17] = 0.f;

    // ---- adjacency path ----
    {
        int pr = tid & 255, q4 = tid >> 8;
        float s = 0.f;
#pragma unroll
        for (int q = q4 * 8; q < q4 * 8 + 8; q++) s += g_gram[q * 256 + pr];
        scratch[tid] = s;
    }
    if (tid < 16) {
        float s = 0.f;
#pragma unroll
        for (int q = 0; q < 32; q++) s += g_colsum[q * 16 + tid];
        cm[tid] = s * (1.f / 512.f);
    }
    __syncthreads();
    if (tid < 256) {
        float G = scratch[tid] + scratch[256 + tid] + scratch[512 + tid] + scratch[768 + tid];
        int i = tid >> 4, j = tid & 15;
        covs[tid] = G - 512.f * cm[i] * cm[j];
    }
    __syncthreads();
    if (tid < 256) {
        int i = tid >> 4, j = tid & 15;
        float si = sqrtf(fmaxf(covs[i * 16 + i], 0.f));
        float sj = sqrtf(fmaxf(covs[j * 16 + j], 0.f));
        float denom = si * sj;
        float c = denom > 0.f ? covs[tid] / denom : 0.f;
        c = fabsf(c);
        if (i == j) c = 0.f;
        corr_s[tid] = c;
    }
    __syncthreads();

    {
        int o = tid & 255, q = tid >> 8;
        float s = 0.f;
        for (int k = q * 64; k < q * 64 + 64; k++) s = fmaf(corr_s[k], Ws1[k * 256 + o], s);
        scratch[q * 256 + o] = s;
    }
    __syncthreads();
    if (tid < 256)
        h1s[tid] = fmaxf(scratch[tid] + scratch[256 + tid] + scratch[512 + tid] + scratch[768 + tid] + bs1[tid], 0.f);
    __syncthreads();

    {
        int o = tid & 127, q = tid >> 7;
        float s = 0.f;
        for (int k = q * 32; k < q * 32 + 32; k++) s = fmaf(h1s[k], Ws2[k * 128 + o], s);
        scratch[q * 128 + o] = s;
    }
    __syncthreads();
    if (tid < 128) {
        float s = bs2[tid];
        for (int q = 0; q < 8; q++) s += scratch[q * 128 + tid];
        h2s[tid] = fmaxf(s, 0.f);
    }
    __syncthreads();

    {
        int o = tid & 255, q = tid >> 8;
        float s = 0.f;
        for (int k = q * 32; k < q * 32 + 32; k++) s = fmaf(h2s[k], Ws3[k * 256 + o], s);
        scratch[q * 256 + o] = s;
    }
    __syncthreads();
    if (tid < 256) {
        float logit = scratch[tid] + scratch[256 + tid] + scratch[512 + tid] + scratch[768 + tid] + bs3[tid];
        float a = 1.f / (1.f + expf(-logit));
        int i = tid >> 4, j = tid & 15;
        float val = (j > i) ? a : 0.f;
        adj_s[tid] = val;
        out_adj[tid] = val;
    }
    __syncthreads();
    if (tid < 240) {
        int v = tid / 15, p = tid - v * 15;
        int g = p + (p >= v ? 1 : 0);
        float m = (adj_s[g * 16 + v] > 0.5f) ? 1.f : 0.f;
        pms[tid] = m;
        g_pm[tid] = m;
    }
    __syncthreads();
    if (tid < 16) {
        float s = 0.f;
        for (int p = 0; p < 15; p++) s += pms[tid * 15 + p];
        g_hp[tid] = (s > 0.f) ? 1.f : 0.f;
    }
}

// ---- mech helpers (fp16, 2-term A-split layer 1, hi-only layer 2) ----
__device__ __forceinline__ void l1_step(const unsigned* W1s, int lane, int ks,
    const unsigned* ahi, const unsigned* alo, float* a, float* b)
{
    int nt0 = 2 * ks, nt1 = nt0 + 1;
    const unsigned* b0p = W1s + (nt0 * 32 + lane) * 2;
    const unsigned* b1p = W1s + (nt1 * 32 + lane) * 2;
    unsigned b0v[2] = { b0p[0], b0p[1] }, b1v[2] = { b1p[0], b1p[1] };
    mma_f16(a, ahi, b0v);
    mma_f16(b, ahi, b1v);
    mma_f16(a, alo, b0v);
    mma_f16(b, alo, b1v);
}

__device__ __forceinline__ void l1_epi_hi(const float* b1s, int lq, int ks,
    const float* a, const float* b, unsigned* a2hi)
{
    float2 bva = *(const float2*)(b1s + (2 * ks) * 8 + 2 * lq);
    float2 bvb = *(const float2*)(b1s + (2 * ks + 1) * 8 + 2 * lq);
    float h0 = fmaxf(a[0] + bva.x, 0.f), h1 = fmaxf(a[1] + bva.y, 0.f);
    float h2 = fmaxf(a[2] + bva.x, 0.f), h3 = fmaxf(a[3] + bva.y, 0.f);
    float h4 = fmaxf(b[0] + bvb.x, 0.f), h5 = fmaxf(b[1] + bvb.y, 0.f);
    float h6 = fmaxf(b[2] + bvb.x, 0.f), h7 = fmaxf(b[3] + bvb.y, 0.f);
    a2hi[0] = pack2h(h0, h1);
    a2hi[1] = pack2h(h2, h3);
    a2hi[2] = pack2h(h4, h5);
    a2hi[3] = pack2h(h6, h7);
}

// ---------------- Kernel M: MECH only (256 blocks, one 2/SM wave) ----------------
__global__ void __launch_bounds__(256, 2) k_main(
    const float* __restrict__ data,
    const float* __restrict__ bm1, const float* __restrict__ bm2,
    const float* __restrict__ Wm3, const float* __restrict__ bm3,
    float* __restrict__ out_pred)
{
    extern __shared__ float sm[];
    int tid = threadIdx.x;
    int sub = blockIdx.x;
    const int bx = sub & 15;
    const int v = sub >> 4;
    unsigned* Wp  = (unsigned*)sm;
    float* b1s  = sm + 5120;
    float* b2s  = sm + 5248;
    float* w3s  = sm + 5312;
    float* pms  = sm + 5376;
    float* rawv = sm + 5392;
    unsigned* Xh  = (unsigned*)(sm + 5520);
    unsigned* Xl  = (unsigned*)(sm + 6672);

    int w = tid >> 5, lane = tid & 31;
    int lq = lane & 3, lg = lane >> 2;

    {
        const float4* src = (const float4*)(g_wpack + v * 5120);
        float4* dst = (float4*)Wp;
        for (int i = tid; i < 1280; i += 256) dst[i] = src[i];
    }
    if (tid < 128) b1s[tid] = bm1[v * 128 + tid];
    if (tid < 64) { b2s[tid] = bm2[v * 64 + tid]; w3s[tid] = Wm3[v * 64 + tid]; }
    if (tid < 16) pms[tid] = (tid < 15) ? g_pm[v * 15 + tid] : 0.f;
    float hp = g_hp[v];
    float b3 = bm3[v];

    const unsigned* W1s = Wp;
    const unsigned* W2s = Wp + 1024;
    int rA = w * 16 + lg;

    for (int tile = 0; tile < 4; tile++) {
        __syncthreads();
        int row0 = bx * 512 + tile * 128;
        for (int idx = tid; idx < 1024; idx += 256) {
            int row = idx >> 3, kp = idx & 7;
            int p0 = 2 * kp, p1 = 2 * kp + 1;
            const float* drow = data + (row0 + row) * 16;
            float v0 = 0.f, v1 = 0.f;
            v0 = drow[p0 + (p0 >= v ? 1 : 0)] * pms[p0];
            if (p1 < 15) v1 = drow[p1 + (p1 >= v ? 1 : 0)] * pms[p1];
            Xh[row * 9 + kp] = pack2h(v0, v1);
            Xl[row * 9 + kp] = pack2h(v0 - hround(v0), v1 - hround(v1));
        }
        if (tid < 128) rawv[tid] = data[(row0 + tid) * 16 + v];
        __syncthreads();

        unsigned ahi[4], alo[4];
        ahi[0] = Xh[rA * 9 + lq];           ahi[1] = Xh[(rA + 8) * 9 + lq];
        ahi[2] = Xh[rA * 9 + lq + 4];       ahi[3] = Xh[(rA + 8) * 9 + lq + 4];
        alo[0] = Xl[rA * 9 + lq];           alo[1] = Xl[(rA + 8) * 9 + lq];
        alo[2] = Xl[rA * 9 + lq + 4];       alo[3] = Xl[(rA + 8) * 9 + lq + 4];

        float acc2[8][4];
#pragma unroll
        for (int nt = 0; nt < 8; nt++)
#pragma unroll
            for (int i = 0; i < 4; i++) acc2[nt][i] = 0.f;

        unsigned c2hi[4];
        {
            float a1[4] = {0.f, 0.f, 0.f, 0.f}, b1r[4] = {0.f, 0.f, 0.f, 0.f};
            l1_step(W1s, lane, 0, ahi, alo, a1, b1r);
            l1_epi_hi(b1s, lq, 0, a1, b1r, c2hi);
        }
#pragma unroll
        for (int ks = 0; ks < 8; ks++) {
            float n1a[4] = {0.f, 0.f, 0.f, 0.f}, n1b[4] = {0.f, 0.f, 0.f, 0.f};
            if (ks < 7) l1_step(W1s, lane, ks + 1, ahi, alo, n1a, n1b);
#pragma unroll
            for (int nt = 0; nt < 8; nt++) {
                const unsigned* bp = W2s + (ks * 256 + nt * 32 + lane) * 2;
                unsigned bv[2] = { bp[0], bp[1] };
                mma_f16(acc2[nt], c2hi, bv);
            }
            if (ks < 7) l1_epi_hi(b1s, lq, ks + 1, n1a, n1b, c2hi);
        }

        float sA = 0.f, sB = 0.f;
#pragma unroll
        for (int nt = 0; nt < 8; nt++) {
            float2 bv = *(const float2*)(b2s + nt * 8 + 2 * lq);
            float2 wv = *(const float2*)(w3s + nt * 8 + 2 * lq);
            sA = fmaf(fmaxf(acc2[nt][0] + bv.x, 0.f), wv.x, sA);
            sA = fmaf(fmaxf(acc2[nt][1] + bv.y, 0.f), wv.y, sA);
            sB = fmaf(fmaxf(acc2[nt][2] + bv.x, 0.f), wv.x, sB);
            sB = fmaf(fmaxf(acc2[nt][3] + bv.y, 0.f), wv.y, sB);
        }
        sA += __shfl_xor_sync(0xffffffffu, sA, 1);
        sA += __shfl_xor_sync(0xffffffffu, sA, 2);
        sB += __shfl_xor_sync(0xffffffffu, sB, 1);
        sB += __shfl_xor_sync(0xffffffffu, sB, 2);
        if (lq == 0) {
            float pA = (hp > 0.f) ? (sA + b3) : rawv[rA];
            float pB = (hp > 0.f) ? (sB + b3) : rawv[rA + 8];
            out_pred[(row0 + rA) * 16 + v] = pA;
            out_pred[(row0 + rA + 8) * 16 + v] = pB;
        }
    }
}

// ---------------- launch ----------------
extern "C" void kernel_launch(void* const* d_in, const int* in_sizes, int n_in,
                              void* d_out, int out_size) {
    const float* data = (const float*)d_in[0];
    const float* Ws1 = (const float*)d_in[1];
    const float* bs1 = (const float*)d_in[2];
    const float* Ws2 = (const float*)d_in[3];
    const float* bs2 = (const float*)d_in[4];
    const float* Ws3 = (const float*)d_in[5];
    const float* bs3 = (const float*)d_in[6];
    const float* Wm1 = (const float*)d_in[7];
    const float* bm1 = (const float*)d_in[8];
    const float* Wm2 = (const float*)d_in[9];
    const float* bm2 = (const float*)d_in[10];
    const float* Wm3 = (const float*)d_in[11];
    const float* bm3 = (const float*)d_in[12];
    const float* Wt1 = (const float*)d_in[13];
    const float* bt1 = (const float*)d_in[14];
    const float* Wt2 = (const float*)d_in[15];
    const float* bt2 = (const float*)d_in[16];

    float* out = (float*)d_out;
    float* out_adj    = out;
    float* out_pred   = out + 256;
    float* out_scores = out + 256 + 131072;

    cudaFuncSetAttribute(k_main, cudaFuncAttributeMaxDynamicSharedMemorySize, 31296);

    k_prep<<<216, 256, 12800>>>(Wm1, Wm2, data, Wt1, bt1, Wt2, bt2);
    k_adj<<<1, 1024>>>(Ws1, bs1, Ws2, bs2, Ws3, bs3, out_adj, out_scores);
    k_main<<<256, 256, 31296>>>(data, bm1, bm2, Wm3, bm3, out_pred);
}